// round 7
// baseline (speedup 1.0000x reference)
#include <cuda_runtime.h>
#include <cuda_bf16.h>
#include <float.h>

// Problem constants
#define B_   16
#define C_   256
#define H_   128
#define W_   128
#define HW_  (H_ * W_)           // 16384
#define HW4_ (HW_ / 4)           // 4096 float4 pixel-groups per batch
#define KSZ  7
#define PAD  3

#define NB        512            // persistent grid (co-resident: 4 CTAs/SM max, 512<=592)
#define GROUP_B   2              // batches per chunk (32 MiB of x, L2-resident)
#define NCHUNK    (B_ / GROUP_B) // 8
#define TILE_PG   16             // pixel-groups per tile (64 pixels = half a row)

// Scratch maps (per batch, per pixel)
__device__ float g_max[B_ * HW_];   // 1 MiB
__device__ float g_avg[B_ * HW_];   // 1 MiB

// Per (batch,row) ready counters: row ready when == 2 (two half-row tiles)
__device__ unsigned g_flag[B_ * H_];

// One-shot start barrier state (generation-based: replay-safe)
__device__ unsigned g_bar_cnt = 0;
__device__ volatile unsigned g_bar_gen = 0;

__device__ __forceinline__ void grid_barrier() {
    __syncthreads();
    if (threadIdx.x == 0) {
        unsigned gen = g_bar_gen;
        __threadfence();
        if (atomicAdd(&g_bar_cnt, 1u) == NB - 1u) {
            g_bar_cnt = 0u;
            __threadfence();
            g_bar_gen = gen + 1u;
        } else {
            while (g_bar_gen == gen) { __nanosleep(64); }
            __threadfence();
        }
    }
    __syncthreads();
}

// ---------------------------------------------------------------------------
// Persistent kernel, barrier-free pipeline:
//   per chunk: phase1 (reduce own tile, signal row flag)
//              phase2 (wait <=7 halo row flags, conv+gate, multiply 256 ch)
// x re-reads in phase2 hit L2 (loaded by phase1 of the same chunk).
// ---------------------------------------------------------------------------
__global__ void __launch_bounds__(256, 4)
fused_kernel(const float* __restrict__ x,
             const float* __restrict__ conv_w,
             const float* __restrict__ conv_b,
             float* __restrict__ out) {
    __shared__ float4 s_mx[256];
    __shared__ float4 s_sm[256];
    __shared__ float  s_w[2 * KSZ * KSZ];
    __shared__ __align__(16) float s_gate[TILE_PG * 4];  // 64 gates
    __shared__ float  s_bias;

    if (threadIdx.x < 2 * KSZ * KSZ) s_w[threadIdx.x] = conv_w[threadIdx.x];
    if (threadIdx.x == 0) s_bias = conv_b[0];

    // Zero the flags, then one global barrier so nobody signals before zeroing.
    {
        int idx = blockIdx.x * 256 + threadIdx.x;
        if (idx < B_ * H_) g_flag[idx] = 0u;
    }
    grid_barrier();

    const int t    = blockIdx.x;           // 0..511
    const int b_l  = t >> 8;               // local batch within chunk (0/1)
    const int tib  = t & 255;              // tile within batch
    const int pg0  = tib * TILE_PG;        // first pixel-group of tile
    const int hrow = tib >> 1;             // pixel row of this tile (64px = half row)

    for (int chunk = 0; chunk < NCHUNK; chunk++) {
        const int b = chunk * GROUP_B + b_l;

        // ================= Phase 1: channel reduction for this tile ========
        {
            const int px = threadIdx.x & 15;   // pixel-group within tile
            const int cs = threadIdx.x >> 4;   // channel slice 0..15 (16 ch each)
            const int pg = pg0 + px;

            const float4* __restrict__ xb =
                reinterpret_cast<const float4*>(x)
                + ((size_t)(b * C_ + cs * 16)) * HW4_ + pg;

            float4 mx = make_float4(-FLT_MAX, -FLT_MAX, -FLT_MAX, -FLT_MAX);
            float4 sm = make_float4(0.f, 0.f, 0.f, 0.f);

            #pragma unroll
            for (int grp = 0; grp < 2; grp++) {      // 2 groups of 8 channels (MLP=8)
                float4 v[8];
                #pragma unroll
                for (int u = 0; u < 8; u++)
                    v[u] = xb[(size_t)(grp * 8 + u) * HW4_];
                #pragma unroll
                for (int u = 0; u < 8; u++) {
                    mx.x = fmaxf(mx.x, v[u].x); sm.x += v[u].x;
                    mx.y = fmaxf(mx.y, v[u].y); sm.y += v[u].y;
                    mx.z = fmaxf(mx.z, v[u].z); sm.z += v[u].z;
                    mx.w = fmaxf(mx.w, v[u].w); sm.w += v[u].w;
                }
            }

            s_mx[threadIdx.x] = mx;
            s_sm[threadIdx.x] = sm;

            #pragma unroll
            for (int sh = 8; sh >= 1; sh >>= 1) {
                __syncthreads();
                if (threadIdx.x < sh * 16) {
                    float4 omx = s_mx[threadIdx.x + sh * 16];
                    float4 osm = s_sm[threadIdx.x + sh * 16];
                    float4 a = s_mx[threadIdx.x];
                    float4 s = s_sm[threadIdx.x];
                    a.x = fmaxf(a.x, omx.x); s.x += osm.x;
                    a.y = fmaxf(a.y, omx.y); s.y += osm.y;
                    a.z = fmaxf(a.z, omx.z); s.z += osm.z;
                    a.w = fmaxf(a.w, omx.w); s.w += osm.w;
                    s_mx[threadIdx.x] = a;
                    s_sm[threadIdx.x] = s;
                }
            }

            if (threadIdx.x < 16) {
                float4 fm = s_mx[threadIdx.x];
                float4 fs = s_sm[threadIdx.x];
                const float inv_c = 1.0f / (float)C_;
                fs.x *= inv_c; fs.y *= inv_c; fs.z *= inv_c; fs.w *= inv_c;
                reinterpret_cast<float4*>(g_max)[b * HW4_ + pg0 + threadIdx.x] = fm;
                reinterpret_cast<float4*>(g_avg)[b * HW4_ + pg0 + threadIdx.x] = fs;
            }
            __syncthreads();               // all map stores issued
            if (threadIdx.x == 0) {
                __threadfence();           // release: maps visible before flag
                atomicAdd(&g_flag[b * H_ + hrow], 1u);
            }
        }

        // ======== Phase 2: wait halo rows, gates + broadcast multiply ======
        {
            const int hlo = (hrow - PAD < 0) ? 0 : hrow - PAD;
            const int hhi = (hrow + PAD > H_ - 1) ? H_ - 1 : hrow + PAD;
            const int nrows = hhi - hlo + 1;           // <= 7
            if ((int)threadIdx.x < nrows) {
                unsigned* f = &g_flag[b * H_ + hlo + threadIdx.x];
                while (atomicAdd(f, 0u) < 2u) { __nanosleep(32); }
                __threadfence();           // acquire: maps now readable
            }
            __syncthreads();

            // 2a: threads 0..63 compute the tile's 64 gates
            if (threadIdx.x < TILE_PG * 4) {
                const int p = pg0 * 4 + threadIdx.x;
                const int h = p >> 7;
                const int w = p & (W_ - 1);
                const float* __restrict__ mp = g_max + b * HW_;
                const float* __restrict__ ap = g_avg + b * HW_;

                float acc = s_bias;
                #pragma unroll
                for (int kh = 0; kh < KSZ; kh++) {
                    int hh = h + kh - PAD;
                    if (hh < 0 || hh >= H_) continue;
                    int rowoff = hh * W_;
                    #pragma unroll
                    for (int kw = 0; kw < KSZ; kw++) {
                        int ww = w + kw - PAD;
                        if (ww < 0 || ww >= W_) continue;
                        int q = rowoff + ww;
                        acc = fmaf(s_w[kh * KSZ + kw],      mp[q], acc);
                        acc = fmaf(s_w[49 + kh * KSZ + kw], ap[q], acc);
                    }
                }
                s_gate[threadIdx.x] =
                    fminf(fmaxf(acc + 3.0f, 0.0f), 6.0f) * (1.0f / 6.0f);
            }
            __syncthreads();

            // 2b: multiply all 256 channels for this tile (x from L2).
            const int pg_l = threadIdx.x & 15;
            const int c0   = threadIdx.x >> 4;
            const int pg   = pg0 + pg_l;
            const float4 gv = reinterpret_cast<float4*>(s_gate)[pg_l];

            const float4* __restrict__ xb =
                reinterpret_cast<const float4*>(x) + ((size_t)b * C_) * HW4_ + pg;
            float4* __restrict__ ob =
                reinterpret_cast<float4*>(out) + ((size_t)b * C_) * HW4_ + pg;

            #pragma unroll
            for (int grp = 0; grp < 2; grp++) {      // 2 groups of 8 channels (MLP=8)
                float4 v[8];
                int cbase = c0 + grp * 128;          // c = c0 + u*16 (+128)
                #pragma unroll
                for (int u = 0; u < 8; u++)
                    v[u] = __ldcs(xb + (size_t)(cbase + u * 16) * HW4_);
                #pragma unroll
                for (int u = 0; u < 8; u++) {
                    float4 ov;
                    ov.x = v[u].x * gv.x;
                    ov.y = v[u].y * gv.y;
                    ov.z = v[u].z * gv.z;
                    ov.w = v[u].w * gv.w;
                    __stcs(ob + (size_t)(cbase + u * 16) * HW4_, ov);
                }
            }
            __syncthreads();   // s_gate reuse safety for next chunk
        }
    }
}

// ---------------------------------------------------------------------------
extern "C" void kernel_launch(void* const* d_in, const int* in_sizes, int n_in,
                              void* d_out, int out_size) {
    const float* x      = (const float*)d_in[0];  // [16,256,128,128]
    const float* conv_w = (const float*)d_in[1];  // [1,2,7,7] = 98 floats
    const float* conv_b = (const float*)d_in[2];  // [1]
    float* out = (float*)d_out;

    fused_kernel<<<NB, 256>>>(x, conv_w, conv_b, out);
}

// round 8
// speedup vs baseline: 1.1738x; 1.1738x over previous
#include <cuda_runtime.h>
#include <cuda_bf16.h>
#include <float.h>

// Problem constants
#define B_   16
#define C_   256
#define H_   128
#define W_   128
#define HW_  (H_ * W_)           // 16384
#define HW4_ (HW_ / 4)           // 4096 float4 pixel-groups per batch
#define KSZ  7
#define PAD  3

#define NB        512            // persistent grid (co-resident: 4 CTAs/SM, 512<=592)
#define GROUP_B   2              // batches per chunk (32 MiB of x)
#define NCHUNK    (B_ / GROUP_B) // 8
#define TILE_PG   16             // pixel-groups per tile (64 pixels = half a row)

// Scratch maps (per batch, per pixel)
__device__ float g_max[B_ * HW_];   // 1 MiB
__device__ float g_avg[B_ * HW_];   // 1 MiB

// Per (batch,row) ready counters: row ready when == 2 (two half-row tiles)
__device__ unsigned g_flag[B_ * H_];

// One-shot start barrier (generation-based: replay-safe)
__device__ unsigned g_bar_cnt = 0;
__device__ volatile unsigned g_bar_gen = 0;

__device__ __forceinline__ void grid_barrier() {
    __syncthreads();
    if (threadIdx.x == 0) {
        unsigned gen = g_bar_gen;
        __threadfence();
        if (atomicAdd(&g_bar_cnt, 1u) == NB - 1u) {
            g_bar_cnt = 0u;
            __threadfence();
            g_bar_gen = gen + 1u;
        } else {
            while (g_bar_gen == gen) { __nanosleep(64); }
            __threadfence();
        }
    }
    __syncthreads();
}

// ---------------------------------------------------------------------------
// Persistent kernel, software-pipelined one chunk deep:
//   iter k: phase1(chunk k)  -> reduce own tile, signal row flag
//           phase2(chunk k-1)-> flags signaled a full iteration ago (no stall),
//                               conv+gate, multiply 256 channels (x from L2)
//   epilogue: phase2(last chunk)
// ---------------------------------------------------------------------------
__global__ void __launch_bounds__(256, 4)
fused_kernel(const float* __restrict__ x,
             const float* __restrict__ conv_w,
             const float* __restrict__ conv_b,
             float* __restrict__ out) {
    __shared__ float4 s_mx[256];
    __shared__ float4 s_sm[256];
    __shared__ float  s_w[2 * KSZ * KSZ];
    __shared__ __align__(16) float s_gate[TILE_PG * 4];  // 64 gates
    __shared__ float  s_bias;

    if (threadIdx.x < 2 * KSZ * KSZ) s_w[threadIdx.x] = conv_w[threadIdx.x];
    if (threadIdx.x == 0) s_bias = conv_b[0];

    // Zero flags, then one global barrier so nobody signals before zeroing.
    {
        int idx = blockIdx.x * 256 + threadIdx.x;
        if (idx < B_ * H_) g_flag[idx] = 0u;
    }
    grid_barrier();

    const int t    = blockIdx.x;           // 0..511
    const int b_l  = t >> 8;               // local batch within chunk (0/1)
    const int tib  = t & 255;              // tile within batch
    const int pg0  = tib * TILE_PG;        // first pixel-group of tile
    const int hrow = tib >> 1;             // pixel row of this tile

    const int px   = threadIdx.x & 15;     // pixel-group within tile
    const int cs   = threadIdx.x >> 4;     // channel slice 0..15
    const int hlo  = (hrow - PAD < 0) ? 0 : hrow - PAD;
    const int hhi  = (hrow + PAD > H_ - 1) ? H_ - 1 : hrow + PAD;
    const int nrows = hhi - hlo + 1;       // <= 7

    for (int k = 0; k <= NCHUNK; k++) {
        // ================= Phase 1: channel reduction, chunk k =============
        if (k < NCHUNK) {
            const int b  = k * GROUP_B + b_l;
            const int pg = pg0 + px;

            const float4* __restrict__ xb =
                reinterpret_cast<const float4*>(x)
                + ((size_t)(b * C_ + cs * 16)) * HW4_ + pg;

            float4 mx = make_float4(-FLT_MAX, -FLT_MAX, -FLT_MAX, -FLT_MAX);
            float4 sm = make_float4(0.f, 0.f, 0.f, 0.f);

            #pragma unroll
            for (int grp = 0; grp < 2; grp++) {      // 2 x 8 channels (MLP=8)
                float4 v[8];
                #pragma unroll
                for (int u = 0; u < 8; u++)
                    v[u] = xb[(size_t)(grp * 8 + u) * HW4_];
                #pragma unroll
                for (int u = 0; u < 8; u++) {
                    mx.x = fmaxf(mx.x, v[u].x); sm.x += v[u].x;
                    mx.y = fmaxf(mx.y, v[u].y); sm.y += v[u].y;
                    mx.z = fmaxf(mx.z, v[u].z); sm.z += v[u].z;
                    mx.w = fmaxf(mx.w, v[u].w); sm.w += v[u].w;
                }
            }

            s_mx[threadIdx.x] = mx;
            s_sm[threadIdx.x] = sm;

            #pragma unroll
            for (int sh = 8; sh >= 1; sh >>= 1) {
                __syncthreads();
                if (threadIdx.x < sh * 16) {
                    float4 omx = s_mx[threadIdx.x + sh * 16];
                    float4 osm = s_sm[threadIdx.x + sh * 16];
                    float4 a = s_mx[threadIdx.x];
                    float4 s = s_sm[threadIdx.x];
                    a.x = fmaxf(a.x, omx.x); s.x += osm.x;
                    a.y = fmaxf(a.y, omx.y); s.y += osm.y;
                    a.z = fmaxf(a.z, omx.z); s.z += osm.z;
                    a.w = fmaxf(a.w, omx.w); s.w += osm.w;
                    s_mx[threadIdx.x] = a;
                    s_sm[threadIdx.x] = s;
                }
            }

            if (threadIdx.x < 16) {
                float4 fm = s_mx[threadIdx.x];
                float4 fs = s_sm[threadIdx.x];
                const float inv_c = 1.0f / (float)C_;
                fs.x *= inv_c; fs.y *= inv_c; fs.z *= inv_c; fs.w *= inv_c;
                reinterpret_cast<float4*>(g_max)[b * HW4_ + pg0 + threadIdx.x] = fm;
                reinterpret_cast<float4*>(g_avg)[b * HW4_ + pg0 + threadIdx.x] = fs;
            }
            __syncthreads();               // all map stores issued
            if (threadIdx.x == 0) {
                __threadfence();           // release: maps visible before flag
                atomicAdd(&g_flag[b * H_ + hrow], 1u);
            }
        }

        // ============ Phase 2: gates + multiply, chunk k-1 =================
        if (k > 0) {
            const int b = (k - 1) * GROUP_B + b_l;

            // Wait halo rows (signaled a full iteration ago -> rarely blocks)
            if ((int)threadIdx.x < nrows) {
                unsigned* f = &g_flag[b * H_ + hlo + threadIdx.x];
                while (atomicAdd(f, 0u) < 2u) { __nanosleep(32); }
                __threadfence();           // acquire
            }
            __syncthreads();

            // 2a: threads 0..63 compute the tile's 64 gates
            if (threadIdx.x < TILE_PG * 4) {
                const int p = pg0 * 4 + threadIdx.x;
                const int h = p >> 7;
                const int w = p & (W_ - 1);
                const float* __restrict__ mp = g_max + b * HW_;
                const float* __restrict__ ap = g_avg + b * HW_;

                float acc = s_bias;
                #pragma unroll
                for (int kh = 0; kh < KSZ; kh++) {
                    int hh = h + kh - PAD;
                    if (hh < 0 || hh >= H_) continue;
                    int rowoff = hh * W_;
                    #pragma unroll
                    for (int kw = 0; kw < KSZ; kw++) {
                        int ww = w + kw - PAD;
                        if (ww < 0 || ww >= W_) continue;
                        int q = rowoff + ww;
                        acc = fmaf(s_w[kh * KSZ + kw],      mp[q], acc);
                        acc = fmaf(s_w[49 + kh * KSZ + kw], ap[q], acc);
                    }
                }
                s_gate[threadIdx.x] =
                    fminf(fmaxf(acc + 3.0f, 0.0f), 6.0f) * (1.0f / 6.0f);
            }
            __syncthreads();

            // 2b: multiply all 256 channels for this tile (x from L2).
            const int pg = pg0 + px;
            const float4 gv = reinterpret_cast<float4*>(s_gate)[px];

            const float4* __restrict__ xb =
                reinterpret_cast<const float4*>(x) + ((size_t)b * C_) * HW4_ + pg;
            float4* __restrict__ ob =
                reinterpret_cast<float4*>(out) + ((size_t)b * C_) * HW4_ + pg;

            #pragma unroll
            for (int grp = 0; grp < 2; grp++) {      // 2 x 8 channels (MLP=8)
                float4 v[8];
                int cbase = cs + grp * 128;          // c = cs + u*16 (+128)
                #pragma unroll
                for (int u = 0; u < 8; u++)
                    v[u] = __ldcs(xb + (size_t)(cbase + u * 16) * HW4_);
                #pragma unroll
                for (int u = 0; u < 8; u++) {
                    float4 ov;
                    ov.x = v[u].x * gv.x;
                    ov.y = v[u].y * gv.y;
                    ov.z = v[u].z * gv.z;
                    ov.w = v[u].w * gv.w;
                    __stcs(ob + (size_t)(cbase + u * 16) * HW4_, ov);
                }
            }
            __syncthreads();   // s_gate / s_mx reuse safety for next iteration
        }
    }
}

// ---------------------------------------------------------------------------
extern "C" void kernel_launch(void* const* d_in, const int* in_sizes, int n_in,
                              void* d_out, int out_size) {
    const float* x      = (const float*)d_in[0];  // [16,256,128,128]
    const float* conv_w = (const float*)d_in[1];  // [1,2,7,7] = 98 floats
    const float* conv_b = (const float*)d_in[2];  // [1]
    float* out = (float*)d_out;

    fused_kernel<<<NB, 256>>>(x, conv_w, conv_b, out);
}